// round 7
// baseline (speedup 1.0000x reference)
#include <cuda_runtime.h>
#include <cuda_bf16.h>
#include <cuda_fp16.h>
#include <mma.h>
#include <cstdint>

using namespace nvcuda;

#define FDIM 256
#define HEADS 4
#define HEAD_DIM 64
#define NEG_SLOPE 0.2f
#define MAX_N 50000
#define MAX_E 800000
#define SCAN_B 1024
#define MAX_BLKS ((MAX_N + SCAN_B - 1) / SCAN_B)

// GEMM tile config
#define BM 64
#define BN 256
#define BK 64
#define LDA 72    // bf16 elems per A smem row (64 + 8 pad)
#define LDB 264   // bf16 elems per B smem row (256 + 8 pad)
#define LDO 260   // fp32 elems per epilogue smem row

// ---------------- scratch (static __device__, allocation-free) --------------
__device__ __align__(16) __half g_h16[MAX_N * FDIM];            // 25.6 MB
__device__ __align__(16) float g_asrc[MAX_N * HEADS];
__device__ __align__(16) float g_adst[MAX_N * HEADS];
__device__ __align__(16) float g_denom[MAX_N * HEADS];
__device__ __align__(16) float g_anum[(MAX_E + MAX_N) * HEADS]; // 13.6 MB
__device__ __align__(16) __nv_bfloat16 g_bhi[FDIM * FDIM];      // W hi [k][n]
__device__ __align__(16) __nv_bfloat16 g_blo[FDIM * FDIM];      // W lo [k][n]
__device__ int g_count[MAX_N];
__device__ int g_rowstart[MAX_N + 1];
__device__ int g_cursor[MAX_N];
__device__ int g_esrc[MAX_E + MAX_N];
__device__ int g_blocksum[MAX_BLKS];
__device__ int g_blockoff[MAX_BLKS + 1];
__device__ int g_is64;

__device__ __forceinline__ float lrelu(float v) { return v > 0.0f ? v : NEG_SLOPE * v; }

__device__ __forceinline__ int load_idx(const void* ei, long long pos, int is64, int N) {
    int v;
    if (is64) v = (int)((const long long*)ei)[pos];
    else      v = ((const int*)ei)[pos];
    v = v < 0 ? 0 : (v >= N ? N - 1 : v);
    return v;
}

__device__ __forceinline__ uint32_t pack2bf(float a, float b) {
    __nv_bfloat162 t = __floats2bfloat162_rn(a, b);
    return *(uint32_t*)&t;
}

__device__ __forceinline__ void red_add_v4(float* addr, float a, float b, float c, float d) {
    asm volatile("red.global.add.v4.f32 [%0], {%1,%2,%3,%4};"
                 :: "l"(addr), "f"(a), "f"(b), "f"(c), "f"(d) : "memory");
}

__device__ __forceinline__ void cp_async16(void* smem_dst, const void* gptr) {
    uint32_t sa;
    asm("{ .reg .u64 t; cvta.to.shared.u64 t, %1; cvt.u32.u64 %0, t; }" : "=r"(sa) : "l"(smem_dst));
    asm volatile("cp.async.cg.shared.global [%0], [%1], 16;" :: "r"(sa), "l"(gptr) : "memory");
}

// ---------------------------------------------------------------------------
// W -> bf16 hi/lo split (same [k][n] layout as W)
// ---------------------------------------------------------------------------
__global__ void wtrans_kernel(const float* __restrict__ W) {
    int idx = blockIdx.x * blockDim.x + threadIdx.x;
    if (idx >= FDIM * FDIM) return;
    float v = W[idx];
    __nv_bfloat16 hi = __float2bfloat16_rn(v);
    g_bhi[idx] = hi;
    g_blo[idx] = __float2bfloat16_rn(v - __bfloat162float(hi));
}

__global__ void detect_kernel(const unsigned int* __restrict__ w, int nwords) {
    __shared__ int nz;
    if (threadIdx.x == 0) nz = 0;
    __syncthreads();
    int idx = 2 * threadIdx.x + 1;
    if (idx < nwords && idx < 512 && w[idx] != 0u) nz = 1;
    __syncthreads();
    if (threadIdx.x == 0) g_is64 = !nz;
}

__global__ void zero_kernel(int N) {
    int i = blockIdx.x * blockDim.x + threadIdx.x;
    if (i < N) g_count[i] = 0;
    if (i < N * HEADS) g_denom[i] = 0.0f;
}

// ---------------------------------------------------------------------------
// WMMA bf16 split GEMM + fused epilogue (h fp16 + att dots).
// CTA: 256 threads (8 warps, 2x4 warp grid of 32x64 tiles), tile 64x256, BK=64.
// ---------------------------------------------------------------------------
#define GEMM_SMEM ((2 * BM * LDA + 2 * BK * LDB) * 2)  // 86016 bytes

__global__ __launch_bounds__(256, 2)
void gemm_tc_kernel(const float* __restrict__ x,
                    const float* __restrict__ att_src,
                    const float* __restrict__ att_dst, int M) {
    extern __shared__ char smem[];
    __nv_bfloat16* Ahi = (__nv_bfloat16*)smem;
    __nv_bfloat16* Alo = Ahi + BM * LDA;
    __nv_bfloat16* Bhi = Alo + BM * LDA;
    __nv_bfloat16* Blo = Bhi + BK * LDB;
    float* s_out = (float*)smem;  // reused after mainloop
    __shared__ float s_src[FDIM], s_dst[FDIM];

    int tid = threadIdx.x;
    int wid = tid >> 5;
    int wm = wid >> 2, wn = wid & 3;   // warp tile (wm*32, wn*64)
    int row0 = blockIdx.x * BM;

    s_src[tid] = att_src[tid];
    s_dst[tid] = att_dst[tid];

    wmma::fragment<wmma::accumulator, 16, 16, 16, float> c[2][4];
#pragma unroll
    for (int i = 0; i < 2; i++)
#pragma unroll
        for (int j = 0; j < 4; j++) wmma::fill_fragment(c[i][j], 0.0f);

    int ar = tid >> 2, acg = (tid & 3) * 16;     // A fill: row, 16-col group
    int bk = tid >> 2, bcg = (tid & 3) * 64;     // B fill: k-row, 64-col group

    for (int c4 = 0; c4 < 4; c4++) {
        int k0 = c4 * BK;
        // B tile: pre-split bf16, plain cp.async copies (overlap with A cvt)
        {
            const __nv_bfloat16* bh = &g_bhi[(size_t)(k0 + bk) * FDIM + bcg];
            const __nv_bfloat16* bl = &g_blo[(size_t)(k0 + bk) * FDIM + bcg];
#pragma unroll
            for (int j = 0; j < 8; j++) {
                cp_async16(&Bhi[bk * LDB + bcg + j * 8], bh + j * 8);
                cp_async16(&Blo[bk * LDB + bcg + j * 8], bl + j * 8);
            }
            asm volatile("cp.async.commit_group;" ::: "memory");
        }
        // A tile: x[row0+ar][k0+acg..+16) -> hi/lo bf16
        {
            int r = row0 + ar;
            const float4* xp = (r < M) ? (const float4*)&x[(size_t)r * FDIM + k0 + acg] : nullptr;
#pragma unroll
            for (int j = 0; j < 4; j++) {
                float4 v = xp ? xp[j] : make_float4(0.f, 0.f, 0.f, 0.f);
                __nv_bfloat16 h0 = __float2bfloat16_rn(v.x), h1 = __float2bfloat16_rn(v.y);
                __nv_bfloat16 h2 = __float2bfloat16_rn(v.z), h3 = __float2bfloat16_rn(v.w);
                uint2 phi, plo;
                phi.x = pack2bf(__bfloat162float(h0), __bfloat162float(h1));
                phi.y = pack2bf(__bfloat162float(h2), __bfloat162float(h3));
                plo.x = pack2bf(v.x - __bfloat162float(h0), v.y - __bfloat162float(h1));
                plo.y = pack2bf(v.z - __bfloat162float(h2), v.w - __bfloat162float(h3));
                *(uint2*)&Ahi[ar * LDA + acg + j * 4] = phi;
                *(uint2*)&Alo[ar * LDA + acg + j * 4] = plo;
            }
        }
        asm volatile("cp.async.wait_group 0;" ::: "memory");
        __syncthreads();

#pragma unroll
        for (int ks = 0; ks < 4; ks++) {
            wmma::fragment<wmma::matrix_a, 16, 16, 16, __nv_bfloat16, wmma::row_major> ah[2], al[2];
#pragma unroll
            for (int i = 0; i < 2; i++) {
                wmma::load_matrix_sync(ah[i], &Ahi[(wm * 32 + i * 16) * LDA + ks * 16], LDA);
                wmma::load_matrix_sync(al[i], &Alo[(wm * 32 + i * 16) * LDA + ks * 16], LDA);
            }
#pragma unroll
            for (int j = 0; j < 4; j++) {
                wmma::fragment<wmma::matrix_b, 16, 16, 16, __nv_bfloat16, wmma::row_major> bh, bl;
                wmma::load_matrix_sync(bh, &Bhi[(ks * 16) * LDB + wn * 64 + j * 16], LDB);
                wmma::load_matrix_sync(bl, &Blo[(ks * 16) * LDB + wn * 64 + j * 16], LDB);
#pragma unroll
                for (int i = 0; i < 2; i++) {
                    wmma::mma_sync(c[i][j], ah[i], bh, c[i][j]);
                    wmma::mma_sync(c[i][j], ah[i], bl, c[i][j]);
                    wmma::mma_sync(c[i][j], al[i], bh, c[i][j]);
                }
            }
        }
        __syncthreads();
    }

    // ---- epilogue: acc -> smem fp32 ----
#pragma unroll
    for (int i = 0; i < 2; i++)
#pragma unroll
        for (int j = 0; j < 4; j++)
            wmma::store_matrix_sync(&s_out[(wm * 32 + i * 16) * LDO + wn * 64 + j * 16],
                                    c[i][j], LDO, wmma::mem_row_major);
    __syncthreads();

    // 128 threads: thread t handles row t/2, cols half*128..+128 (2 heads)
    if (tid < 128) {
        int r = tid >> 1, half = tid & 1;
        int row = row0 + r;
        if (row < M) {
            const float* so = s_out + r * LDO + half * 128;
            const float* sp = s_src + half * 128;
            const float* dp = s_dst + half * 128;
            float psA = 0.f, pdA = 0.f, psB = 0.f, pdB = 0.f;
            uint32_t pk[64];
#pragma unroll
            for (int cc = 0; cc < 64; cc++) {
                float v = so[cc];
                psA = fmaf(v, sp[cc], psA);
                pdA = fmaf(v, dp[cc], pdA);
                if (cc & 1) {
                    __half2 t = __floats2half2_rn(so[cc - 1], v);
                    pk[cc >> 1] = *(uint32_t*)&t;
                }
            }
#pragma unroll
            for (int cc = 64; cc < 128; cc++) {
                float v = so[cc];
                psB = fmaf(v, sp[cc], psB);
                pdB = fmaf(v, dp[cc], pdB);
                if (cc & 1) {
                    __half2 t = __floats2half2_rn(so[cc - 1], v);
                    pk[cc >> 1] = *(uint32_t*)&t;
                }
            }
            uint4* hp = (uint4*)&g_h16[(size_t)row * FDIM + half * 128];
#pragma unroll
            for (int q = 0; q < 16; q++)
                hp[q] = make_uint4(pk[4 * q], pk[4 * q + 1], pk[4 * q + 2], pk[4 * q + 3]);
            *(float2*)&g_asrc[row * 4 + half * 2] = make_float2(psA, psB);
            *(float2*)&g_adst[row * 4 + half * 2] = make_float2(pdA, pdB);
        }
    }
}

// ---------------------------------------------------------------------------
__global__ void hist_kernel(const void* __restrict__ ei, int E, int N) {
    int e = blockIdx.x * blockDim.x + threadIdx.x;
    int ET = E + N;
    if (e >= ET) return;
    int d = (e < E) ? load_idx(ei, (long long)E + e, g_is64, N) : e - E;
    atomicAdd(&g_count[d], 1);
}

__global__ void scan1_kernel(int N) {
    __shared__ int sh[32];
    int i = blockIdx.x * SCAN_B + threadIdx.x;
    int v = (i < N) ? g_count[i] : 0;
#pragma unroll
    for (int sft = 16; sft; sft >>= 1) v += __shfl_xor_sync(0xFFFFFFFF, v, sft);
    if ((threadIdx.x & 31) == 0) sh[threadIdx.x >> 5] = v;
    __syncthreads();
    if (threadIdx.x < 32) {
        int w = (threadIdx.x < SCAN_B / 32) ? sh[threadIdx.x] : 0;
#pragma unroll
        for (int sft = 16; sft; sft >>= 1) w += __shfl_xor_sync(0xFFFFFFFF, w, sft);
        if (threadIdx.x == 0) g_blocksum[blockIdx.x] = w;
    }
}

__global__ void scan2_kernel(int nblks) {
    if (threadIdx.x == 0) {
        int run = 0;
        for (int b = 0; b < nblks; b++) {
            g_blockoff[b] = run;
            run += g_blocksum[b];
        }
        g_blockoff[nblks] = run;
    }
}

__global__ void scan3_kernel(int N) {
    __shared__ int warpsum[32];
    int i = blockIdx.x * SCAN_B + threadIdx.x;
    int lane = threadIdx.x & 31, wid = threadIdx.x >> 5;
    int v = (i < N) ? g_count[i] : 0;
    int x = v;
#pragma unroll
    for (int sft = 1; sft < 32; sft <<= 1) {
        int y = __shfl_up_sync(0xFFFFFFFF, x, sft);
        if (lane >= sft) x += y;
    }
    if (lane == 31) warpsum[wid] = x;
    __syncthreads();
    if (wid == 0) {
        int w = (lane < SCAN_B / 32) ? warpsum[lane] : 0;
#pragma unroll
        for (int sft = 1; sft < 32; sft <<= 1) {
            int y = __shfl_up_sync(0xFFFFFFFF, w, sft);
            if (lane >= sft) w += y;
        }
        if (lane < SCAN_B / 32) warpsum[lane] = w;
    }
    __syncthreads();
    int excl = x - v + (wid ? warpsum[wid - 1] : 0) + g_blockoff[blockIdx.x];
    if (i < N) {
        g_rowstart[i] = excl;
        g_cursor[i] = excl;
        if (i == N - 1) g_rowstart[N] = excl + v;
    }
}

// ---------------------------------------------------------------------------
// fill: CSR scatter + fused softmax numerators + denominator reduction.
// Runs after gemm (needs g_asrc/g_adst).
// ---------------------------------------------------------------------------
__global__ void fill_kernel(const void* __restrict__ ei, int E, int N) {
    int e = blockIdx.x * blockDim.x + threadIdx.x;
    int ET = E + N;
    if (e >= ET) return;
    int is64 = g_is64;
    int s, d;
    if (e < E) {
        s = load_idx(ei, e, is64, N);
        d = load_idx(ei, (long long)E + e, is64, N);
    } else s = d = e - E;
    int pos = atomicAdd(&g_cursor[d], 1);
    g_esrc[pos] = s;
    float4 as = *(const float4*)&g_asrc[s * 4];
    float4 ad = *(const float4*)&g_adst[d * 4];
    float4 nu;
    nu.x = __expf(lrelu(as.x + ad.x));
    nu.y = __expf(lrelu(as.y + ad.y));
    nu.z = __expf(lrelu(as.z + ad.z));
    nu.w = __expf(lrelu(as.w + ad.w));
    *(float4*)&g_anum[(size_t)pos * 4] = nu;
    red_add_v4(&g_denom[d * 4], nu.x, nu.y, nu.z, nu.w);
}

// ---------------------------------------------------------------------------
// agg: warp per dst node, weighted fp16 gather only (denoms precomputed).
// ---------------------------------------------------------------------------
__global__ void agg_kernel(float* __restrict__ out, const float* __restrict__ bias, int N) {
    int d = (blockIdx.x * blockDim.x + threadIdx.x) >> 5;
    int lane = threadIdx.x & 31;
    if (d >= N) return;
    int row = g_rowstart[d];
    int re  = g_rowstart[d + 1];
    int head = lane >> 3;           // lane covers cols [lane*8, lane*8+8) -> one head
    float4 dn = *(const float4*)&g_denom[d * 4];
    float rs = 1.0f / ((const float*)&dn)[head];

    float acc[8] = {0.f, 0.f, 0.f, 0.f, 0.f, 0.f, 0.f, 0.f};
    for (int i = row; i < re; i++) {
        int s = g_esrc[i];                                   // broadcast
        float4 nu = *(const float4*)&g_anum[(size_t)i * 4];  // broadcast
        float al = ((const float*)&nu)[head] * rs;
        uint4 hv = *(const uint4*)&g_h16[(size_t)s * FDIM + lane * 8];
        const __half2* h2 = (const __half2*)&hv;
#pragma unroll
        for (int q = 0; q < 4; q++) {
            float2 f = __half22float2(h2[q]);
            acc[2 * q]     = fmaf(al, f.x, acc[2 * q]);
            acc[2 * q + 1] = fmaf(al, f.y, acc[2 * q + 1]);
        }
    }
    const float* bp = bias + lane * 8;
    float4 o0 = make_float4(acc[0] + bp[0], acc[1] + bp[1], acc[2] + bp[2], acc[3] + bp[3]);
    float4 o1 = make_float4(acc[4] + bp[4], acc[5] + bp[5], acc[6] + bp[6], acc[7] + bp[7]);
    float4* op = (float4*)(out + (size_t)d * FDIM + lane * 8);
    op[0] = o0;
    op[1] = o1;
}

// ---------------------------------------------------------------------------
extern "C" void kernel_launch(void* const* d_in, const int* in_sizes, int n_in,
                              void* d_out, int out_size) {
    const float* x        = (const float*)d_in[0];
    const void*  ei       = d_in[1];
    const float* W        = (const float*)d_in[2];
    const float* att_src  = (const float*)d_in[3];
    const float* att_dst  = (const float*)d_in[4];
    const float* bias     = (const float*)d_in[5];
    float* out = (float*)d_out;

    int N = in_sizes[0] / FDIM;
    int E = in_sizes[1] / 2;
    int ET = E + N;
    int nblks = (N + SCAN_B - 1) / SCAN_B;

    static int smem_set = 0;
    if (!smem_set) {
        cudaFuncSetAttribute(gemm_tc_kernel, cudaFuncAttributeMaxDynamicSharedMemorySize, GEMM_SMEM);
        smem_set = 1;
    }

    // Order chosen so the 4th launch (ncu capture slot) is the GEMM.
    wtrans_kernel<<<(FDIM * FDIM + 255) / 256, 256>>>(W);
    detect_kernel<<<1, 256>>>((const unsigned int*)ei, in_sizes[1]);
    zero_kernel<<<(N * HEADS + 255) / 256, 256>>>(N);
    gemm_tc_kernel<<<(N + BM - 1) / BM, 256, GEMM_SMEM>>>(x, att_src, att_dst, N);
    hist_kernel<<<(ET + 255) / 256, 256>>>(ei, E, N);
    scan1_kernel<<<nblks, SCAN_B>>>(N);
    scan2_kernel<<<1, 32>>>(nblks);
    scan3_kernel<<<nblks, SCAN_B>>>(N);
    fill_kernel<<<(ET + 255) / 256, 256>>>(ei, E, N);
    agg_kernel<<<((size_t)N * 32 + 255) / 256, 256>>>(out, bias, N);
}

// round 13
// speedup vs baseline: 1.6332x; 1.6332x over previous
#include <cuda_runtime.h>
#include <cuda_bf16.h>
#include <cuda_fp16.h>
#include <mma.h>
#include <cstdint>

using namespace nvcuda;

#define FDIM 256
#define HEADS 4
#define HEAD_DIM 64
#define NEG_SLOPE 0.2f
#define MAX_N 50000
#define PAD_N 50176            // MAX_N rounded up to 128 (tile overrun safety)
#define MAX_E 800000
#define SCAN_B 1024
#define MAX_BLKS ((MAX_N + SCAN_B - 1) / SCAN_B)

// GEMM tile config
#define BM 128
#define BN 128
#define BK 32
#define LDA 40    // 32+8 bf16
#define LDB 136   // 128+8 bf16
#define LDO 132   // fp32 epilogue row
#define A_MAT (BM * LDA)            // 5120 bf16
#define B_MAT (BK * LDB)            // 4352 bf16
#define GEMM_SMEM ((4 * A_MAT + 4 * B_MAT) * 2)   // 75776 bytes

// ---------------- scratch (static __device__, allocation-free) --------------
__device__ __align__(16) __half g_h16[MAX_N * FDIM];            // 25.6 MB
__device__ __align__(16) __nv_bfloat16 g_xhi[PAD_N * FDIM];     // 25.7 MB
__device__ __align__(16) __nv_bfloat16 g_xlo[PAD_N * FDIM];     // 25.7 MB
__device__ __align__(16) float g_asrc[MAX_N * HEADS];
__device__ __align__(16) float g_adst[MAX_N * HEADS];
__device__ __align__(16) float g_denom[MAX_N * HEADS];
__device__ __align__(16) float g_anum[(MAX_E + MAX_N) * HEADS]; // 13.6 MB
__device__ __align__(16) __nv_bfloat16 g_bhi[FDIM * FDIM];      // W hi [k][n]
__device__ __align__(16) __nv_bfloat16 g_blo[FDIM * FDIM];      // W lo [k][n]
__device__ int g_count[MAX_N];
__device__ int g_rowstart[MAX_N + 1];
__device__ int g_cursor[MAX_N];
__device__ int g_esrc[MAX_E + MAX_N];
__device__ int g_blocksum[MAX_BLKS];
__device__ int g_blockoff[MAX_BLKS + 1];
__device__ int g_is64;

__device__ __forceinline__ float lrelu(float v) { return v > 0.0f ? v : NEG_SLOPE * v; }

__device__ __forceinline__ int load_idx(const void* ei, long long pos, int is64, int N) {
    int v;
    if (is64) v = (int)((const long long*)ei)[pos];
    else      v = ((const int*)ei)[pos];
    v = v < 0 ? 0 : (v >= N ? N - 1 : v);
    return v;
}

__device__ __forceinline__ void red_add_v4(float* addr, float a, float b, float c, float d) {
    asm volatile("red.global.add.v4.f32 [%0], {%1,%2,%3,%4};"
                 :: "l"(addr), "f"(a), "f"(b), "f"(c), "f"(d) : "memory");
}

__device__ __forceinline__ void cp_async16(void* smem_dst, const void* gptr) {
    uint32_t sa;
    asm("{ .reg .u64 t; cvta.to.shared.u64 t, %1; cvt.u32.u64 %0, t; }" : "=r"(sa) : "l"(smem_dst));
    asm volatile("cp.async.cg.shared.global [%0], [%1], 16;" :: "r"(sa), "l"(gptr) : "memory");
}

// ---------------------------------------------------------------------------
// W -> bf16 hi/lo split (same [k][n] layout as W)
// ---------------------------------------------------------------------------
__global__ void wtrans_kernel(const float* __restrict__ W) {
    int idx = blockIdx.x * blockDim.x + threadIdx.x;
    if (idx >= FDIM * FDIM) return;
    float v = W[idx];
    __nv_bfloat16 hi = __float2bfloat16_rn(v);
    g_bhi[idx] = hi;
    g_blo[idx] = __float2bfloat16_rn(v - __bfloat162float(hi));
}

// ---------------------------------------------------------------------------
// x -> bf16 hi/lo split
// ---------------------------------------------------------------------------
__global__ void xsplit_kernel(const float* __restrict__ x, int total) {
    int i = (blockIdx.x * blockDim.x + threadIdx.x) * 4;
    if (i >= total) return;
    float4 v = *(const float4*)&x[i];
    __nv_bfloat16 h0 = __float2bfloat16_rn(v.x), h1 = __float2bfloat16_rn(v.y);
    __nv_bfloat16 h2 = __float2bfloat16_rn(v.z), h3 = __float2bfloat16_rn(v.w);
    __nv_bfloat162 hi01 = {h0, h1}, hi23 = {h2, h3};
    __nv_bfloat162 lo01 = __floats2bfloat162_rn(v.x - __bfloat162float(h0), v.y - __bfloat162float(h1));
    __nv_bfloat162 lo23 = __floats2bfloat162_rn(v.z - __bfloat162float(h2), v.w - __bfloat162float(h3));
    *(uint2*)&g_xhi[i] = make_uint2(*(uint32_t*)&hi01, *(uint32_t*)&hi23);
    *(uint2*)&g_xlo[i] = make_uint2(*(uint32_t*)&lo01, *(uint32_t*)&lo23);
}

__global__ void detect_kernel(const unsigned int* __restrict__ w, int nwords) {
    __shared__ int nz;
    if (threadIdx.x == 0) nz = 0;
    __syncthreads();
    int idx = 2 * threadIdx.x + 1;
    if (idx < nwords && idx < 512 && w[idx] != 0u) nz = 1;
    __syncthreads();
    if (threadIdx.x == 0) g_is64 = !nz;
}

__global__ void zero_kernel(int N) {
    int i = blockIdx.x * blockDim.x + threadIdx.x;
    if (i < N) g_count[i] = 0;
    if (i < N * HEADS) g_denom[i] = 0.0f;
}

// ---------------------------------------------------------------------------
// Double-buffered WMMA bf16 split GEMM + fused epilogue.
// CTA: 256 threads (8 warps, 4x2 grid of 32x64 warp tiles), tile 128x128.
// grid = (ceil(M/128), 2): y selects N half (heads 2y, 2y+1).
// Pure cp.async fills from pre-split g_xhi/g_xlo/g_bhi/g_blo; 8 K-chunks.
// ---------------------------------------------------------------------------
__device__ __forceinline__ void gemm_issue_chunk(char* smem, int buf, int k0,
                                                 int row0, int col0, int tid) {
    __nv_bfloat16* sA = (__nv_bfloat16*)smem;
    __nv_bfloat16* sB = sA + 4 * A_MAT;
    // A: 512 16B-units per matrix (row = u>>2, part = u&3)
#pragma unroll
    for (int t = 0; t < 2; t++) {
        int u = tid + t * 256;
        int row = u >> 2, part = u & 3;
        size_t src = (size_t)(row0 + row) * FDIM + k0 + part * 8;
        int dst = (buf * 2) * A_MAT + row * LDA + part * 8;
        cp_async16(&sA[dst], &g_xhi[src]);
        cp_async16(&sA[dst + A_MAT], &g_xlo[src]);
    }
    // B: 512 16B-units per matrix (krow = u>>4, part = u&15)
#pragma unroll
    for (int t = 0; t < 2; t++) {
        int u = tid + t * 256;
        int krow = u >> 4, part = u & 15;
        size_t src = (size_t)(k0 + krow) * FDIM + col0 + part * 8;
        int dst = (buf * 2) * B_MAT + krow * LDB + part * 8;
        cp_async16(&sB[dst], &g_bhi[src]);
        cp_async16(&sB[dst + B_MAT], &g_blo[src]);
    }
    asm volatile("cp.async.commit_group;" ::: "memory");
}

__global__ __launch_bounds__(256, 2)
void gemm_tc_kernel(const float* __restrict__ att_src,
                    const float* __restrict__ att_dst, int M) {
    extern __shared__ char smem[];
    __nv_bfloat16* sA = (__nv_bfloat16*)smem;
    __nv_bfloat16* sB = sA + 4 * A_MAT;
    float* s_out = (float*)smem;  // reused after mainloop (67.6KB <= 75.8KB)
    __shared__ float s_src[BN], s_dst[BN];

    int tid = threadIdx.x;
    int wid = tid >> 5;
    int wm = wid >> 1, wn = wid & 1;   // warp tile (wm*32, wn*64)
    int row0 = blockIdx.x * BM;
    int col0 = blockIdx.y * BN;

    if (tid < BN) {
        s_src[tid] = att_src[col0 + tid];
        s_dst[tid] = att_dst[col0 + tid];
    }

    wmma::fragment<wmma::accumulator, 16, 16, 16, float> c[2][4];
#pragma unroll
    for (int i = 0; i < 2; i++)
#pragma unroll
        for (int j = 0; j < 4; j++) wmma::fill_fragment(c[i][j], 0.0f);

    gemm_issue_chunk(smem, 0, 0, row0, col0, tid);

    for (int ch = 0; ch < 8; ch++) {
        if (ch < 7) {
            gemm_issue_chunk(smem, (ch + 1) & 1, (ch + 1) * BK, row0, col0, tid);
            asm volatile("cp.async.wait_group 1;" ::: "memory");
        } else {
            asm volatile("cp.async.wait_group 0;" ::: "memory");
        }
        __syncthreads();

        int b = ch & 1;
        const __nv_bfloat16* Ahi = sA + (b * 2) * A_MAT;
        const __nv_bfloat16* Alo = Ahi + A_MAT;
        const __nv_bfloat16* Bhi = sB + (b * 2) * B_MAT;
        const __nv_bfloat16* Blo = Bhi + B_MAT;

#pragma unroll
        for (int ks = 0; ks < 2; ks++) {
            wmma::fragment<wmma::matrix_a, 16, 16, 16, __nv_bfloat16, wmma::row_major> ah[2], al[2];
#pragma unroll
            for (int i = 0; i < 2; i++) {
                wmma::load_matrix_sync(ah[i], &Ahi[(wm * 32 + i * 16) * LDA + ks * 16], LDA);
                wmma::load_matrix_sync(al[i], &Alo[(wm * 32 + i * 16) * LDA + ks * 16], LDA);
            }
#pragma unroll
            for (int j = 0; j < 4; j++) {
                wmma::fragment<wmma::matrix_b, 16, 16, 16, __nv_bfloat16, wmma::row_major> bh, bl;
                wmma::load_matrix_sync(bh, &Bhi[(ks * 16) * LDB + wn * 64 + j * 16], LDB);
                wmma::load_matrix_sync(bl, &Blo[(ks * 16) * LDB + wn * 64 + j * 16], LDB);
#pragma unroll
                for (int i = 0; i < 2; i++) {
                    wmma::mma_sync(c[i][j], ah[i], bh, c[i][j]);
                    wmma::mma_sync(c[i][j], ah[i], bl, c[i][j]);
                    wmma::mma_sync(c[i][j], al[i], bh, c[i][j]);
                }
            }
        }
        __syncthreads();  // protect buf b before it is refilled at iter ch+1
    }

    // ---- epilogue: acc -> smem fp32 ----
#pragma unroll
    for (int i = 0; i < 2; i++)
#pragma unroll
        for (int j = 0; j < 4; j++)
            wmma::store_matrix_sync(&s_out[(wm * 32 + i * 16) * LDO + wn * 64 + j * 16],
                                    c[i][j], LDO, wmma::mem_row_major);
    __syncthreads();

    // 256 threads: thread t -> row t>>1, half (t&1) = one head (64 cols)
    {
        int r = tid >> 1, half = tid & 1;
        int row = row0 + r;
        if (row < M) {
            const float* so = s_out + r * LDO + half * 64;
            const float* sp = s_src + half * 64;
            const float* dp = s_dst + half * 64;
            float ps = 0.f, pd = 0.f;
            uint32_t pk[32];
#pragma unroll
            for (int cc = 0; cc < 64; cc++) {
                float v = so[cc];
                ps = fmaf(v, sp[cc], ps);
                pd = fmaf(v, dp[cc], pd);
                if (cc & 1) {
                    __half2 t2 = __floats2half2_rn(so[cc - 1], v);
                    pk[cc >> 1] = *(uint32_t*)&t2;
                }
            }
            uint4* hp = (uint4*)&g_h16[(size_t)row * FDIM + col0 + half * 64];
#pragma unroll
            for (int q = 0; q < 8; q++)
                hp[q] = make_uint4(pk[4 * q], pk[4 * q + 1], pk[4 * q + 2], pk[4 * q + 3]);
            int head = blockIdx.y * 2 + half;
            g_asrc[row * 4 + head] = ps;
            g_adst[row * 4 + head] = pd;
        }
    }
}

// ---------------------------------------------------------------------------
__global__ void hist_kernel(const void* __restrict__ ei, int E, int N) {
    int e = blockIdx.x * blockDim.x + threadIdx.x;
    int ET = E + N;
    if (e >= ET) return;
    int d = (e < E) ? load_idx(ei, (long long)E + e, g_is64, N) : e - E;
    atomicAdd(&g_count[d], 1);
}

__global__ void scan1_kernel(int N) {
    __shared__ int sh[32];
    int i = blockIdx.x * SCAN_B + threadIdx.x;
    int v = (i < N) ? g_count[i] : 0;
#pragma unroll
    for (int sft = 16; sft; sft >>= 1) v += __shfl_xor_sync(0xFFFFFFFF, v, sft);
    if ((threadIdx.x & 31) == 0) sh[threadIdx.x >> 5] = v;
    __syncthreads();
    if (threadIdx.x < 32) {
        int w = (threadIdx.x < SCAN_B / 32) ? sh[threadIdx.x] : 0;
#pragma unroll
        for (int sft = 16; sft; sft >>= 1) w += __shfl_xor_sync(0xFFFFFFFF, w, sft);
        if (threadIdx.x == 0) g_blocksum[blockIdx.x] = w;
    }
}

__global__ void scan2_kernel(int nblks) {
    if (threadIdx.x == 0) {
        int run = 0;
        for (int b = 0; b < nblks; b++) {
            g_blockoff[b] = run;
            run += g_blocksum[b];
        }
        g_blockoff[nblks] = run;
    }
}

__global__ void scan3_kernel(int N) {
    __shared__ int warpsum[32];
    int i = blockIdx.x * SCAN_B + threadIdx.x;
    int lane = threadIdx.x & 31, wid = threadIdx.x >> 5;
    int v = (i < N) ? g_count[i] : 0;
    int x = v;
#pragma unroll
    for (int sft = 1; sft < 32; sft <<= 1) {
        int y = __shfl_up_sync(0xFFFFFFFF, x, sft);
        if (lane >= sft) x += y;
    }
    if (lane == 31) warpsum[wid] = x;
    __syncthreads();
    if (wid == 0) {
        int w = (lane < SCAN_B / 32) ? warpsum[lane] : 0;
#pragma unroll
        for (int sft = 1; sft < 32; sft <<= 1) {
            int y = __shfl_up_sync(0xFFFFFFFF, w, sft);
            if (lane >= sft) w += y;
        }
        if (lane < SCAN_B / 32) warpsum[lane] = w;
    }
    __syncthreads();
    int excl = x - v + (wid ? warpsum[wid - 1] : 0) + g_blockoff[blockIdx.x];
    if (i < N) {
        g_rowstart[i] = excl;
        g_cursor[i] = excl;
        if (i == N - 1) g_rowstart[N] = excl + v;
    }
}

// ---------------------------------------------------------------------------
// fill: CSR scatter + fused softmax numerators + denominator reduction.
// ---------------------------------------------------------------------------
__global__ void fill_kernel(const void* __restrict__ ei, int E, int N) {
    int e = blockIdx.x * blockDim.x + threadIdx.x;
    int ET = E + N;
    if (e >= ET) return;
    int is64 = g_is64;
    int s, d;
    if (e < E) {
        s = load_idx(ei, e, is64, N);
        d = load_idx(ei, (long long)E + e, is64, N);
    } else s = d = e - E;
    int pos = atomicAdd(&g_cursor[d], 1);
    g_esrc[pos] = s;
    float4 as = *(const float4*)&g_asrc[s * 4];
    float4 ad = *(const float4*)&g_adst[d * 4];
    float4 nu;
    nu.x = __expf(lrelu(as.x + ad.x));
    nu.y = __expf(lrelu(as.y + ad.y));
    nu.z = __expf(lrelu(as.z + ad.z));
    nu.w = __expf(lrelu(as.w + ad.w));
    *(float4*)&g_anum[(size_t)pos * 4] = nu;
    red_add_v4(&g_denom[d * 4], nu.x, nu.y, nu.z, nu.w);
}

// ---------------------------------------------------------------------------
// agg: warp per dst node, weighted fp16 gather only (denoms precomputed).
// ---------------------------------------------------------------------------
__global__ void agg_kernel(float* __restrict__ out, const float* __restrict__ bias, int N) {
    int d = (blockIdx.x * blockDim.x + threadIdx.x) >> 5;
    int lane = threadIdx.x & 31;
    if (d >= N) return;
    int row = g_rowstart[d];
    int re  = g_rowstart[d + 1];
    int head = lane >> 3;           // lane covers cols [lane*8, lane*8+8) -> one head
    float4 dn = *(const float4*)&g_denom[d * 4];
    float rs = 1.0f / ((const float*)&dn)[head];

    float acc[8] = {0.f, 0.f, 0.f, 0.f, 0.f, 0.f, 0.f, 0.f};
    for (int i = row; i < re; i++) {
        int s = g_esrc[i];                                   // broadcast
        float4 nu = *(const float4*)&g_anum[(size_t)i * 4];  // broadcast
        float al = ((const float*)&nu)[head] * rs;
        uint4 hv = *(const uint4*)&g_h16[(size_t)s * FDIM + lane * 8];
        const __half2* h2 = (const __half2*)&hv;
#pragma unroll
        for (int q = 0; q < 4; q++) {
            float2 f = __half22float2(h2[q]);
            acc[2 * q]     = fmaf(al, f.x, acc[2 * q]);
            acc[2 * q + 1] = fmaf(al, f.y, acc[2 * q + 1]);
        }
    }
    const float* bp = bias + lane * 8;
    float4 o0 = make_float4(acc[0] + bp[0], acc[1] + bp[1], acc[2] + bp[2], acc[3] + bp[3]);
    float4 o1 = make_float4(acc[4] + bp[4], acc[5] + bp[5], acc[6] + bp[6], acc[7] + bp[7]);
    float4* op = (float4*)(out + (size_t)d * FDIM + lane * 8);
    op[0] = o0;
    op[1] = o1;
}

// ---------------------------------------------------------------------------
extern "C" void kernel_launch(void* const* d_in, const int* in_sizes, int n_in,
                              void* d_out, int out_size) {
    const float* x        = (const float*)d_in[0];
    const void*  ei       = d_in[1];
    const float* W        = (const float*)d_in[2];
    const float* att_src  = (const float*)d_in[3];
    const float* att_dst  = (const float*)d_in[4];
    const float* bias     = (const float*)d_in[5];
    float* out = (float*)d_out;

    int N = in_sizes[0] / FDIM;
    int E = in_sizes[1] / 2;
    int ET = E + N;
    int nblks = (N + SCAN_B - 1) / SCAN_B;

    // Unconditional (no static guards — harness rule). Cheap, capture-legal.
    cudaFuncSetAttribute(gemm_tc_kernel, cudaFuncAttributeMaxDynamicSharedMemorySize, GEMM_SMEM);

    // Order chosen so the 4th launch (ncu capture slot) is the GEMM.
    wtrans_kernel<<<(FDIM * FDIM + 255) / 256, 256>>>(W);
    xsplit_kernel<<<(N * FDIM / 4 + 255) / 256, 256>>>(x, N * FDIM);
    detect_kernel<<<1, 256>>>((const unsigned int*)ei, in_sizes[1]);
    dim3 ggrid((N + BM - 1) / BM, FDIM / BN);
    gemm_tc_kernel<<<ggrid, 256, GEMM_SMEM>>>(att_src, att_dst, N);
    zero_kernel<<<(N * HEADS + 255) / 256, 256>>>(N);
    hist_kernel<<<(ET + 255) / 256, 256>>>(ei, E, N);
    scan1_kernel<<<nblks, SCAN_B>>>(N);
    scan2_kernel<<<1, 32>>>(nblks);
    scan3_kernel<<<nblks, SCAN_B>>>(N);
    fill_kernel<<<(ET + 255) / 256, 256>>>(ei, E, N);
    agg_kernel<<<((size_t)N * 32 + 255) / 256, 256>>>(out, bias, N);
}